// round 2
// baseline (speedup 1.0000x reference)
#include <cuda_runtime.h>

// RegL1Loss: out[b] = sum_{p,d} valid * |preds[b, idx] - val| / num_people[b]
// B=32, P=64, D=34, L=1048576. gts packed as [...,3] = (val, idx_as_float, flag).

#define B 32
#define P 64
#define D 34
#define PD (P * D)        // 2176
#define L 1048576
#define NTHREADS 256

__global__ __launch_bounds__(NTHREADS) void regl1_kernel(
    const float* __restrict__ preds,
    const float* __restrict__ gts,
    float* __restrict__ out)
{
    const int b = blockIdx.x;
    const int tid = threadIdx.x;

    __shared__ int person_valid[P];
    __shared__ float warp_sums[NTHREADS / 32];

    if (tid < P) person_valid[tid] = 0;
    __syncthreads();

    const float* g  = gts   + (size_t)b * PD * 3;
    const float* pr = preds + (size_t)b * L;

    float acc = 0.0f;
    #pragma unroll
    for (int e = tid; e < PD; e += NTHREADS) {
        // 3 consecutive floats per element
        float val  = g[e * 3 + 0];
        float fidx = g[e * 3 + 1];
        float flag = g[e * 3 + 2];
        if (flag > 0.0f) {
            int idx = (int)fidx;
            float gathered = __ldg(pr + idx);
            acc += fabsf(gathered - val);
            person_valid[e / D] = 1;   // benign race: all writers store 1
        }
    }

    // warp-level reduce acc
    #pragma unroll
    for (int off = 16; off > 0; off >>= 1)
        acc += __shfl_xor_sync(0xFFFFFFFFu, acc, off);

    const int wid = tid >> 5;
    const int lid = tid & 31;
    if (lid == 0) warp_sums[wid] = acc;
    __syncthreads();

    if (wid == 0) {
        // total loss
        float total = (lid < NTHREADS / 32) ? warp_sums[lid] : 0.0f;
        #pragma unroll
        for (int off = 16; off > 0; off >>= 1)
            total += __shfl_xor_sync(0xFFFFFFFFu, total, off);

        // num_people: each lane sums 2 entries of person_valid
        int cnt = person_valid[lid] + person_valid[lid + 32];
        #pragma unroll
        for (int off = 16; off > 0; off >>= 1)
            cnt += __shfl_xor_sync(0xFFFFFFFFu, cnt, off);

        if (lid == 0)
            out[b] = total / (float)cnt;
    }
}

extern "C" void kernel_launch(void* const* d_in, const int* in_sizes, int n_in,
                              void* d_out, int out_size)
{
    const float* preds = (const float*)d_in[0];
    const float* gts   = (const float*)d_in[1];
    float* out = (float*)d_out;
    regl1_kernel<<<B, NTHREADS>>>(preds, gts, out);
}